// round 7
// baseline (speedup 1.0000x reference)
#include <cuda_runtime.h>
#include <math.h>

// Quincunx lattice max pooling:
//   coset0, coset1: [B=4, C=32, H=512, W=512] fp32
//   out:            [2, B, C, H, W] fp32   (out0 then out1)
//
// out0[i,j] = max(c0[i,j], c0[i+1,j], c0[i,j+1], c0[i+1,j+1], c1[i,j])
// out1[i,j] = max(c1[i,j], c1[i+1,j], c1[i,j+1], c1[i+1,j+1], c0[i+1,j+1])
// OOB -> -inf.
//
// R6: persistent grid-stride kernel, unit = 2 output rows x 1 float4 x both
// cosets (6 vector loads). Next iteration's loads are prefetched before the
// current iteration's compute+store, keeping a dense DRAM request stream.
// Grid chosen so total units is an exact multiple of thread count (uniform
// trip count -> convergent shuffles, no per-iter bounds checks).

#define HH   512
#define WW   512
#define W4   128          // float4 per row
#define PP   256          // row pairs per image
#define NEGINF __int_as_float(0xff800000)

#define GBLK 1024
#define GTHR 256

struct Unit {
    float4 a0, a1, a2, b0, b1, b2;
    long   base;
    int    flags;         // bit0: last_pair, bit1: last_col
};

__device__ __forceinline__ void load_unit(const float4* __restrict__ c0,
                                          const float4* __restrict__ c1,
                                          long u, Unit& t)
{
    int jv  = (int)(u & (W4 - 1));
    int p   = (int)((u >> 7) & (PP - 1));
    long img = u >> 15;
    long base = img * (long)(HH * W4) + (long)(2 * p) * W4 + jv;
    bool last_pair = (p == PP - 1);
    const float ni = NEGINF;
    const float4 ni4 = make_float4(ni, ni, ni, ni);

    t.a0 = c0[base];
    t.a1 = c0[base + W4];
    t.b0 = c1[base];
    t.b1 = c1[base + W4];
    t.a2 = last_pair ? ni4 : c0[base + 2 * W4];
    t.b2 = last_pair ? ni4 : c1[base + 2 * W4];
    t.base  = base;
    t.flags = (last_pair ? 1 : 0) | ((jv == W4 - 1) ? 2 : 0);
}

__device__ __forceinline__ void process_unit(const float4* __restrict__ c0,
                                             const float4* __restrict__ c1,
                                             float4* __restrict__ out0,
                                             float4* __restrict__ out1,
                                             const Unit& t, int lane)
{
    const float ni = NEGINF;
    const unsigned m = 0xffffffffu;
    float a0n = __shfl_down_sync(m, t.a0.x, 1);
    float a1n = __shfl_down_sync(m, t.a1.x, 1);
    float a2n = __shfl_down_sync(m, t.a2.x, 1);
    float b0n = __shfl_down_sync(m, t.b0.x, 1);
    float b1n = __shfl_down_sync(m, t.b1.x, 1);
    float b2n = __shfl_down_sync(m, t.b2.x, 1);

    if (lane == 31) {
        if (!(t.flags & 2)) {       // not last column
            const float* c0s = (const float*)c0;
            const float* c1s = (const float*)c1;
            long e = t.base * 4 + 4;
            a0n = __ldg(c0s + e);
            a1n = __ldg(c0s + e + WW);
            b0n = __ldg(c1s + e);
            b1n = __ldg(c1s + e + WW);
            if (!(t.flags & 1)) {
                a2n = __ldg(c0s + e + 2 * WW);
                b2n = __ldg(c1s + e + 2 * WW);
            } else {
                a2n = ni; b2n = ni;
            }
        } else {
            a0n = a1n = a2n = b0n = b1n = b2n = ni;
        }
    }

    float4 r;
    // out0 row 2p
    {
        float vx = fmaxf(t.a0.x, t.a1.x), vy = fmaxf(t.a0.y, t.a1.y);
        float vz = fmaxf(t.a0.z, t.a1.z), vw = fmaxf(t.a0.w, t.a1.w);
        float vn = fmaxf(a0n, a1n);
        r.x = fmaxf(fmaxf(vx, vy), t.b0.x);
        r.y = fmaxf(fmaxf(vy, vz), t.b0.y);
        r.z = fmaxf(fmaxf(vz, vw), t.b0.z);
        r.w = fmaxf(fmaxf(vw, vn), t.b0.w);
        out0[t.base] = r;
    }
    // out1 row 2p
    {
        float vx = fmaxf(t.b0.x, t.b1.x), vy = fmaxf(t.b0.y, t.b1.y);
        float vz = fmaxf(t.b0.z, t.b1.z), vw = fmaxf(t.b0.w, t.b1.w);
        float vn = fmaxf(b0n, b1n);
        r.x = fmaxf(fmaxf(vx, vy), t.a1.y);
        r.y = fmaxf(fmaxf(vy, vz), t.a1.z);
        r.z = fmaxf(fmaxf(vz, vw), t.a1.w);
        r.w = fmaxf(fmaxf(vw, vn), a1n);
        out1[t.base] = r;
    }
    // out0 row 2p+1
    {
        float vx = fmaxf(t.a1.x, t.a2.x), vy = fmaxf(t.a1.y, t.a2.y);
        float vz = fmaxf(t.a1.z, t.a2.z), vw = fmaxf(t.a1.w, t.a2.w);
        float vn = fmaxf(a1n, a2n);
        r.x = fmaxf(fmaxf(vx, vy), t.b1.x);
        r.y = fmaxf(fmaxf(vy, vz), t.b1.y);
        r.z = fmaxf(fmaxf(vz, vw), t.b1.z);
        r.w = fmaxf(fmaxf(vw, vn), t.b1.w);
        out0[t.base + W4] = r;
    }
    // out1 row 2p+1
    {
        float vx = fmaxf(t.b1.x, t.b2.x), vy = fmaxf(t.b1.y, t.b2.y);
        float vz = fmaxf(t.b1.z, t.b2.z), vw = fmaxf(t.b1.w, t.b2.w);
        float vn = fmaxf(b1n, b2n);
        r.x = fmaxf(fmaxf(vx, vy), t.a2.y);
        r.y = fmaxf(fmaxf(vy, vz), t.a2.z);
        r.z = fmaxf(fmaxf(vz, vw), t.a2.w);
        r.w = fmaxf(fmaxf(vw, vn), a2n);
        out1[t.base + W4] = r;
    }
}

__global__ void __launch_bounds__(GTHR)
lattice_pool_kernel(const float4* __restrict__ c0,
                    const float4* __restrict__ c1,
                    float4* __restrict__ out0,
                    float4* __restrict__ out1,
                    long total2)
{
    const long stride = (long)GBLK * GTHR;
    long u = (long)blockIdx.x * GTHR + threadIdx.x;
    int lane = threadIdx.x & 31;
    int iters = (int)(total2 / stride);      // exact (total2 = 16 * stride)

    Unit cur, nxt;
    load_unit(c0, c1, u, cur);
    for (int it = 0; it < iters - 1; ++it) {
        long u2 = u + stride;
        load_unit(c0, c1, u2, nxt);          // prefetch next unit
        process_unit(c0, c1, out0, out1, cur, lane);
        cur = nxt;
        u = u2;
    }
    process_unit(c0, c1, out0, out1, cur, lane);
}

extern "C" void kernel_launch(void* const* d_in, const int* in_sizes, int n_in,
                              void* d_out, int out_size)
{
    const float4* c0 = (const float4*)d_in[0];
    const float4* c1 = (const float4*)d_in[1];
    long per_coset4 = in_sizes[0] / 4;         // float4 per coset
    long total2 = per_coset4 / 2;              // 2-row units
    float4* out0 = (float4*)d_out;
    float4* out1 = out0 + per_coset4;

    lattice_pool_kernel<<<GBLK, GTHR>>>(c0, c1, out0, out1, total2);
}

// round 8
// speedup vs baseline: 1.0804x; 1.0804x over previous
#include <cuda_runtime.h>
#include <math.h>

// Quincunx lattice max pooling, shapes fixed by the problem:
//   coset0, coset1: [B=4, C=32, H=512, W=512] fp32
//   out:            [2, B, C, H, W] fp32   (out0 then out1)
//
// out0[i,j] = max(c0[i,j], c0[i+1,j], c0[i,j+1], c0[i+1,j+1], c1[i,j])
// out1[i,j] = max(c1[i,j], c1[i+1,j], c1[i,j+1], c1[i+1,j+1], c0[i+1,j+1])
// OOB -> -inf (ignored).
//
// R7: R4 structure (4 output rows/thread, 5 input rows/coset, shuffle tails,
// lane-31 predicated scalar loads) with WRITE-THROUGH stores (__stwt):
// output never re-read, so bypassing L2 allocation keeps L2 clean for the
// read-side row reuse and feeds DRAM a steady sequential write stream
// instead of bursty dirty-evictions. Block=512.

#define HH   512
#define WW   512
#define W4   128          // float4 per row
#define QQ   128          // row quads per image
#define NEGINF __int_as_float(0xff800000)

__global__ void __launch_bounds__(512)
lattice_pool_kernel(const float4* __restrict__ c0,
                    const float4* __restrict__ c1,
                    float4* __restrict__ out0,
                    float4* __restrict__ out1,
                    int total)   // total threads = B*C*QQ*W4
{
    int idx = blockIdx.x * blockDim.x + threadIdx.x;
    if (idx >= total) return;

    int jv  = idx & (W4 - 1);           // float4 column
    int q   = (idx >> 7) & (QQ - 1);    // row-quad within image
    long img = idx >> 14;               // (b,c) plane index

    long base = img * (long)(HH * W4) + (long)(4 * q) * W4 + jv;
    bool last_quad = (q == QQ - 1);
    bool last_col  = (jv == W4 - 1);
    const float ni = NEGINF;
    const float4 ni4 = make_float4(ni, ni, ni, ni);

    // Five input rows per coset: 4q .. 4q+4
    float4 a[5], b[5];
#pragma unroll
    for (int r = 0; r < 4; r++) {
        a[r] = c0[base + r * W4];
        b[r] = c1[base + r * W4];
    }
    a[4] = last_quad ? ni4 : c0[base + 4 * W4];
    b[4] = last_quad ? ni4 : c1[base + 4 * W4];

    // Horizontal tail (element at column 4*jv+4) via shuffle from lane+1.
    const unsigned m = 0xffffffffu;
    float an[5], bn[5];
#pragma unroll
    for (int r = 0; r < 5; r++) {
        an[r] = __shfl_down_sync(m, a[r].x, 1);
        bn[r] = __shfl_down_sync(m, b[r].x, 1);
    }

    int lane = threadIdx.x & 31;
    if (lane == 31) {
        if (!last_col) {
            const float* c0s = (const float*)c0;
            const float* c1s = (const float*)c1;
            long e = base * 4 + 4;      // scalar idx of col 4*jv+4, row 4q
#pragma unroll
            for (int r = 0; r < 4; r++) {
                an[r] = __ldg(c0s + e + r * WW);
                bn[r] = __ldg(c1s + e + r * WW);
            }
            if (!last_quad) {
                an[4] = __ldg(c0s + e + 4 * WW);
                bn[4] = __ldg(c1s + e + 4 * WW);
            } else {
                an[4] = ni; bn[4] = ni;
            }
        } else {
#pragma unroll
            for (int r = 0; r < 5; r++) { an[r] = ni; bn[r] = ni; }
        }
    }

    // Per output row r (global row 4q+r):
    //   out0: max over c0 rows (r, r+1) cols (j, j+1)  +  c1[r] same-site
    //   out1: max over c1 rows (r, r+1) cols (j, j+1)  +  c0[r+1] down-right
#pragma unroll
    for (int r = 0; r < 4; r++) {
        float4 o;
        // out0
        {
            float vx = fmaxf(a[r].x, a[r + 1].x);
            float vy = fmaxf(a[r].y, a[r + 1].y);
            float vz = fmaxf(a[r].z, a[r + 1].z);
            float vw = fmaxf(a[r].w, a[r + 1].w);
            float vn = fmaxf(an[r], an[r + 1]);
            o.x = fmaxf(fmaxf(vx, vy), b[r].x);
            o.y = fmaxf(fmaxf(vy, vz), b[r].y);
            o.z = fmaxf(fmaxf(vz, vw), b[r].z);
            o.w = fmaxf(fmaxf(vw, vn), b[r].w);
            __stwt(&out0[base + r * W4], o);
        }
        // out1
        {
            float vx = fmaxf(b[r].x, b[r + 1].x);
            float vy = fmaxf(b[r].y, b[r + 1].y);
            float vz = fmaxf(b[r].z, b[r + 1].z);
            float vw = fmaxf(b[r].w, b[r + 1].w);
            float vn = fmaxf(bn[r], bn[r + 1]);
            o.x = fmaxf(fmaxf(vx, vy), a[r + 1].y);
            o.y = fmaxf(fmaxf(vy, vz), a[r + 1].z);
            o.z = fmaxf(fmaxf(vz, vw), a[r + 1].w);
            o.w = fmaxf(fmaxf(vw, vn), an[r + 1]);
            __stwt(&out1[base + r * W4], o);
        }
    }
}

extern "C" void kernel_launch(void* const* d_in, const int* in_sizes, int n_in,
                              void* d_out, int out_size)
{
    const float4* c0 = (const float4*)d_in[0];
    const float4* c1 = (const float4*)d_in[1];
    int per_coset4 = in_sizes[0] / 4;          // float4 per coset
    int total = per_coset4 / 4;                // one thread per 4 output rows x 4 cols
    float4* out0 = (float4*)d_out;
    float4* out1 = out0 + per_coset4;

    int threads = 512;
    int blocks  = (total + threads - 1) / threads;
    lattice_pool_kernel<<<blocks, threads>>>(c0, c1, out0, out1, total);
}